// round 14
// baseline (speedup 1.0000x reference)
#include <cuda_runtime.h>
#include <cuda_bf16.h>
#include <math.h>
#include <stdint.h>

// ---------------- constants ----------------
#define BNUM 64
#define NGRP 128
#define NPER 48
#define EPER 192
#define MAXN 64
#define MAXE 256
#define DIN 32
#define TT 5
#define KK 3
#define VN 6144
#define VE 24576
#define INV_TEMP 10.0f
#define SINK_ITERS 10

// ---------------- scratch layout (floats) ----------------
#define SZ_ENC_N ((size_t)VN * 128)
#define SZ_ENC_E ((size_t)VE * 128)
#define SZ_NS ((size_t)VN * 768)
#define SZ_ES ((size_t)VE * 1536)
#define SZ_UN ((size_t)VN * 768)
#define SZ_UE ((size_t)VE * 1536)
#define SZ_TMPN ((size_t)VN * 256)
#define SZ_TMPE ((size_t)VE * 384)
#define SZ_HC ((size_t)VN * 128)
#define SZ_EC ((size_t)VE * 128)
#define SZ_FWD ((size_t)VE * 256)
#define SZ_AGG ((size_t)VN * 256)
#define SZ_TN ((size_t)NGRP * 64 * 64)
#define SZ_TE ((size_t)NGRP * 256 * 64)
#define SZ_PLN ((size_t)BNUM * 64 * 64)
#define SZ_PLE ((size_t)BNUM * 256 * 256)
#define SZ_WM2 ((size_t)256 * 256 + 256)
#define SZ_CSR ((size_t)(3 * VN + 2 + 2 * VE))

#define OFF_ENC_N ((size_t)0)
#define OFF_ENC_E (OFF_ENC_N + SZ_ENC_N)
#define OFF_NS (OFF_ENC_E + SZ_ENC_E)
#define OFF_ES (OFF_NS + SZ_NS)
#define OFF_UN (OFF_ES + SZ_ES)
#define OFF_UE (OFF_UN + SZ_UN)
#define OFF_TMPN (OFF_UE + SZ_UE)
#define OFF_TMPE (OFF_TMPN + SZ_TMPN)
#define OFF_HC (OFF_TMPE + SZ_TMPE)
#define OFF_EC (OFF_HC + SZ_HC)
#define OFF_FWD (OFF_EC + SZ_EC)
#define OFF_BWD (OFF_FWD + SZ_FWD)
#define OFF_AGG (OFF_BWD + SZ_FWD)
#define OFF_TN (OFF_AGG + SZ_AGG)
#define OFF_TE (OFF_TN + SZ_TN)
#define OFF_PLN (OFF_TE + SZ_TE)
#define OFF_PLE (OFF_PLN + SZ_PLN)
#define OFF_WM2 (OFF_PLE + SZ_PLE)
#define OFF_CSR (OFF_WM2 + SZ_WM2)
#define SCRATCH_TOTAL (OFF_CSR + SZ_CSR)

__device__ __align__(256) float g_scratch[SCRATCH_TOTAL];

// ---------------- mma helpers ----------------
__device__ __forceinline__ uint32_t s2u(const void* p) {
    return (uint32_t)__cvta_generic_to_shared(p);
}

#define LDSM4(r0, r1, r2, r3, addr) \
    asm volatile("ldmatrix.sync.aligned.m8n8.x4.shared.b16 {%0,%1,%2,%3},[%4];" \
                 : "=r"(r0), "=r"(r1), "=r"(r2), "=r"(r3) : "r"(addr))

#define LDSM4T(r0, r1, r2, r3, addr) \
    asm volatile("ldmatrix.sync.aligned.m8n8.x4.trans.shared.b16 {%0,%1,%2,%3},[%4];" \
                 : "=r"(r0), "=r"(r1), "=r"(r2), "=r"(r3) : "r"(addr))

#define MMA16816(c, a, b0, b1) \
    asm volatile("mma.sync.aligned.m16n8k16.row.col.f32.bf16.bf16.f32 " \
                 "{%0,%1,%2,%3},{%4,%5,%6,%7},{%8,%9},{%0,%1,%2,%3};" \
                 : "+f"((c)[0]), "+f"((c)[1]), "+f"((c)[2]), "+f"((c)[3]) \
                 : "r"((a)[0]), "r"((a)[1]), "r"((a)[2]), "r"((a)[3]), "r"(b0), "r"(b1))

__device__ __forceinline__ void split_store4(__nv_bfloat16* ph, __nv_bfloat16* pm, float4 v)
{
    __nv_bfloat16 h0 = __float2bfloat16(v.x);
    __nv_bfloat16 h1 = __float2bfloat16(v.y);
    __nv_bfloat16 h2 = __float2bfloat16(v.z);
    __nv_bfloat16 h3 = __float2bfloat16(v.w);
    ((__nv_bfloat162*)ph)[0] = __nv_bfloat162(h0, h1);
    ((__nv_bfloat162*)ph)[1] = __nv_bfloat162(h2, h3);
    ((__nv_bfloat162*)pm)[0] = __nv_bfloat162(__float2bfloat16(v.x - __bfloat162float(h0)),
                                              __float2bfloat16(v.y - __bfloat162float(h1)));
    ((__nv_bfloat162*)pm)[1] = __nv_bfloat162(__float2bfloat16(v.z - __bfloat162float(h2)),
                                              __float2bfloat16(v.w - __bfloat162float(h3)));
}

// =====================================================================
// bgemm<BM>: tensor-core GEMM, 2-term bf16 split (hi*hi + hi*mid + mid*hi).
// C[M,N] = concat_K(A0|A1|A2) @ B + bias, optional relu.
// Seg [0,kb1)->A0 (gather r0a; if r0b != null, A-rows are A0[r0a]+A0[r0b]),
// [kb1,kb2)->A1 (gather r1a), [kb2,K)->A2 (identity rows).
// Dual mode (gridDim.z==2): z==1 swaps seg0/seg1 gathers, writes C_dual
// (callers must not combine dual with r0b).
// BM=128: 8 warps 4x2 (warp 32x64). BM=64: 8 warps 2x4 (warp 32x32).
// M%BM==0, N%128==0, K%32==0, kb1/kb2 mult of 32, ldb==N, 16B alignment.
// =====================================================================
template <int BM>
__global__ __launch_bounds__(256, 2) void bgemm_kernel(
    const float* __restrict__ A0, int lda0, const int* __restrict__ r0a,
    const int* __restrict__ r0b,
    const float* __restrict__ A1, int lda1, const int* __restrict__ r1a,
    const float* __restrict__ A2, int lda2,
    int kb1, int kb2,
    const float* __restrict__ B,
    const float* __restrict__ bias,
    float* __restrict__ C, float* __restrict__ C_dual, int ldc,
    int Ndim, int Kdim, int relu)
{
    constexpr int WN = (BM == 128) ? 2 : 4;   // warps along n
    constexpr int CP = 128 / WN;              // cols per warp (64 / 32)
    constexpr int NP = CP / 16;               // 16-col pairs per warp (4 / 2)

    __shared__ __align__(16) __nv_bfloat16 Ah[BM][40];
    __shared__ __align__(16) __nv_bfloat16 Am[BM][40];
    __shared__ __align__(16) __nv_bfloat16 Bh[32][136];
    __shared__ __align__(16) __nv_bfloat16 Bm[32][136];
    __shared__ int rows0[BM], rows0b[BM], rows1[BM];

    const int tid = threadIdx.x;
    const int lane = tid & 31;
    const int wid = tid >> 5;
    const int warp_m = wid / WN;
    const int warp_n = wid % WN;
    const int row0 = blockIdx.y * BM;
    const int col0 = blockIdx.x * 128;

    const int* g0 = r0a;
    const int* g1 = r1a;
    float* Cout = C;
    const int* gsum = (blockIdx.z == 0) ? r0b : nullptr;
    if (blockIdx.z == 1) { g0 = r1a; g1 = r0a; Cout = C_dual; }

    if (tid < BM) {
        rows0[tid] = g0 ? __ldg(&g0[row0 + tid]) : (row0 + tid);
        rows0b[tid] = gsum ? __ldg(&gsum[row0 + tid]) : 0;
        rows1[tid] = g1 ? __ldg(&g1[row0 + tid]) : (row0 + tid);
    }
    __syncthreads();

    float acc[2][NP * 2][4];
#pragma unroll
    for (int i = 0; i < 2; i++)
#pragma unroll
        for (int j = 0; j < NP * 2; j++)
#pragma unroll
            for (int l = 0; l < 4; l++) acc[i][j][l] = 0.f;

    for (int k0 = 0; k0 < Kdim; k0 += 32) {
        const float* Ap; int lda; const int* rs; int kloc; bool dosum = false;
        if (k0 < kb1) { Ap = A0; lda = lda0; rs = rows0; kloc = k0; dosum = (gsum != nullptr); }
        else if (k0 < kb2) { Ap = A1; lda = lda1; rs = rows1; kloc = k0 - kb1; }
        else { Ap = A2; lda = lda2; rs = nullptr; kloc = k0 - kb2; }

#pragma unroll
        for (int u = 0; u < BM / 32; u++) {
            int idx = tid + u * 256;
            int m = idx >> 3;
            int kq = (idx & 7) << 2;
            int ar = rs ? rs[m] : (row0 + m);
            float4 v = *(const float4*)(Ap + (size_t)ar * lda + kloc + kq);
            if (dosum) {
                float4 w = *(const float4*)(Ap + (size_t)rows0b[m] * lda + kloc + kq);
                v.x += w.x; v.y += w.y; v.z += w.z; v.w += w.w;
            }
            split_store4(&Ah[m][kq], &Am[m][kq], v);
        }
#pragma unroll
        for (int u = 0; u < 4; u++) {
            int idx = tid + u * 256;
            int kk = idx >> 5;
            int nq = (idx & 31) << 2;
            float4 v = *(const float4*)(B + (size_t)(k0 + kk) * Ndim + col0 + nq);
            split_store4(&Bh[kk][nq], &Bm[kk][nq], v);
        }
        __syncthreads();

#pragma unroll
        for (int h = 0; h < 2; h++) {
            const int kh = h * 16;
            uint32_t ah[2][4], am[2][4];
#pragma unroll
            for (int mt = 0; mt < 2; mt++) {
                int r = warp_m * 32 + mt * 16 + (lane & 15);
                int kc = kh + ((lane >> 4) << 3);
                uint32_t addr = s2u(&Ah[r][kc]);
                LDSM4(ah[mt][0], ah[mt][1], ah[mt][2], ah[mt][3], addr);
                addr = s2u(&Am[r][kc]);
                LDSM4(am[mt][0], am[mt][1], am[mt][2], am[mt][3], addr);
            }
#pragma unroll
            for (int p = 0; p < NP; p++) {
                uint32_t bh[4], bm[4];
                int kr = kh + (lane & 15);
                int cb = warp_n * CP + p * 16 + ((lane >> 4) << 3);
                uint32_t addr = s2u(&Bh[kr][cb]);
                LDSM4T(bh[0], bh[1], bh[2], bh[3], addr);
                addr = s2u(&Bm[kr][cb]);
                LDSM4T(bm[0], bm[1], bm[2], bm[3], addr);
#pragma unroll
                for (int mt = 0; mt < 2; mt++) {
                    MMA16816(acc[mt][p * 2 + 0], ah[mt], bh[0], bh[1]);
                    MMA16816(acc[mt][p * 2 + 0], ah[mt], bm[0], bm[1]);
                    MMA16816(acc[mt][p * 2 + 0], am[mt], bh[0], bh[1]);
                    MMA16816(acc[mt][p * 2 + 1], ah[mt], bh[2], bh[3]);
                    MMA16816(acc[mt][p * 2 + 1], ah[mt], bm[2], bm[3]);
                    MMA16816(acc[mt][p * 2 + 1], am[mt], bh[2], bh[3]);
                }
            }
        }
        __syncthreads();
    }

    const int rbase = row0 + warp_m * 32 + (lane >> 2);
    const int cbase = col0 + warp_n * CP + (lane & 3) * 2;
#pragma unroll
    for (int mt = 0; mt < 2; mt++) {
#pragma unroll
        for (int hf = 0; hf < 2; hf++) {
            int r = rbase + mt * 16 + hf * 8;
            float* crow = Cout + (size_t)r * ldc;
#pragma unroll
            for (int nt = 0; nt < NP * 2; nt++) {
                int c = cbase + nt * 8;
                float v0 = acc[mt][nt][hf * 2 + 0];
                float v1 = acc[mt][nt][hf * 2 + 1];
                if (bias) { v0 += __ldg(&bias[c]); v1 += __ldg(&bias[c + 1]); }
                if (relu) { v0 = fmaxf(v0, 0.f); v1 = fmaxf(v1, 0.f); }
                crow[c] = v0;
                crow[c + 1] = v1;
            }
        }
    }
}

// =====================================================================
// trans_apply_mma: store rows = plan(^T) @ feats, bf16-split tensor cores.
// =====================================================================
__global__ __launch_bounds__(256) void trans_apply_mma(
    const float* __restrict__ plan, const float* __restrict__ upd,
    float* __restrict__ store, int maxr, int nreal, int ld, int coff, int padK)
{
    __shared__ __align__(16) __nv_bfloat16 Ah[64][40];
    __shared__ __align__(16) __nv_bfloat16 Am[64][40];
    __shared__ __align__(16) __nv_bfloat16 Bh[32][136];
    __shared__ __align__(16) __nv_bfloat16 Bm[32][136];

    const int tid = threadIdx.x;
    const int lane = tid & 31;
    const int wid = tid >> 5;
    const int warp_m = wid >> 2;
    const int warp_n = wid & 3;
    const int z = blockIdx.z;
    const int b = z >> 1;
    const int mode = z & 1;
    const float* P = plan + (size_t)b * maxr * maxr;
    const int fgrp = 2 * b + (mode ? 0 : 1);
    const int ogrp = 2 * b + mode;
    const float* F = upd + (size_t)fgrp * nreal * ld + coff;
    float* C = store + (size_t)ogrp * nreal * ld + coff;
    const int row0 = blockIdx.y * 64;
    const int col0 = blockIdx.x * 128;

    float acc[2][4][4];
#pragma unroll
    for (int i = 0; i < 2; i++)
#pragma unroll
        for (int j = 0; j < 4; j++)
#pragma unroll
            for (int l = 0; l < 4; l++) acc[i][j][l] = 0.f;

    for (int k0 = 0; k0 < padK; k0 += 32) {
        if (mode == 0) {
#pragma unroll
            for (int u = 0; u < 2; u++) {
                int idx = tid + u * 256;
                int r = idx >> 3;
                int kq = (idx & 7) << 2;
                float4 v = *(const float4*)(P + (size_t)(row0 + r) * maxr + k0 + kq);
                split_store4(&Ah[r][kq], &Am[r][kq], v);
            }
        } else {
#pragma unroll
            for (int u = 0; u < 8; u++) {
                int idx = tid + u * 256;
                int r = idx & 63;
                int kk = idx >> 6;
                float v = P[(size_t)(k0 + kk) * maxr + row0 + r];
                __nv_bfloat16 h = __float2bfloat16(v);
                Ah[r][kk] = h;
                Am[r][kk] = __float2bfloat16(v - __bfloat162float(h));
            }
        }
#pragma unroll
        for (int u = 0; u < 4; u++) {
            int idx = tid + u * 256;
            int kk = idx >> 5;
            int nq = (idx & 31) << 2;
            int gk = k0 + kk;
            float4 v = make_float4(0.f, 0.f, 0.f, 0.f);
            if (gk < nreal) v = *(const float4*)(F + (size_t)gk * ld + col0 + nq);
            split_store4(&Bh[kk][nq], &Bm[kk][nq], v);
        }
        __syncthreads();

#pragma unroll
        for (int h = 0; h < 2; h++) {
            const int kh = h * 16;
            uint32_t ah[2][4], am[2][4];
#pragma unroll
            for (int mt = 0; mt < 2; mt++) {
                int r = warp_m * 32 + mt * 16 + (lane & 15);
                int kc = kh + ((lane >> 4) << 3);
                uint32_t addr = s2u(&Ah[r][kc]);
                LDSM4(ah[mt][0], ah[mt][1], ah[mt][2], ah[mt][3], addr);
                addr = s2u(&Am[r][kc]);
                LDSM4(am[mt][0], am[mt][1], am[mt][2], am[mt][3], addr);
            }
#pragma unroll
            for (int p = 0; p < 2; p++) {
                uint32_t bh[4], bm[4];
                int kr = kh + (lane & 15);
                int cb = warp_n * 32 + p * 16 + ((lane >> 4) << 3);
                uint32_t addr = s2u(&Bh[kr][cb]);
                LDSM4T(bh[0], bh[1], bh[2], bh[3], addr);
                addr = s2u(&Bm[kr][cb]);
                LDSM4T(bm[0], bm[1], bm[2], bm[3], addr);
#pragma unroll
                for (int mt = 0; mt < 2; mt++) {
                    MMA16816(acc[mt][p * 2 + 0], ah[mt], bh[0], bh[1]);
                    MMA16816(acc[mt][p * 2 + 0], ah[mt], bm[0], bm[1]);
                    MMA16816(acc[mt][p * 2 + 0], am[mt], bh[0], bh[1]);
                    MMA16816(acc[mt][p * 2 + 1], ah[mt], bh[2], bh[3]);
                    MMA16816(acc[mt][p * 2 + 1], ah[mt], bm[2], bm[3]);
                    MMA16816(acc[mt][p * 2 + 1], am[mt], bh[2], bh[3]);
                }
            }
        }
        __syncthreads();
    }

    const int rbase = row0 + warp_m * 32 + (lane >> 2);
    const int cbase = col0 + warp_n * 32 + (lane & 3) * 2;
#pragma unroll
    for (int mt = 0; mt < 2; mt++) {
#pragma unroll
        for (int hf = 0; hf < 2; hf++) {
            int r = rbase + mt * 16 + hf * 8;
            if (r >= nreal) continue;
            float* crow = C + (size_t)r * ld;
#pragma unroll
            for (int nt = 0; nt < 4; nt++) {
                int c = cbase + nt * 8;
                crow[c] = acc[mt][nt][hf * 2 + 0];
                crow[c + 1] = acc[mt][nt][hf * 2 + 1];
            }
        }
    }
}

// ---------------- misc elementwise ----------------
__global__ void zero_kernel(float* __restrict__ p, size_t n) {
    size_t i = (size_t)blockIdx.x * blockDim.x + threadIdx.x;
    size_t stride = (size_t)gridDim.x * blockDim.x;
    for (; i < n; i += stride) p[i] = 0.f;
}

// WM2 = [Wa+Wb ; 2*Wc] (256x256), bias2 = 2*msg_b
__global__ void wm2f_kernel(const float* __restrict__ msgW, float* __restrict__ wm2,
                            const float* __restrict__ msg_b, float* __restrict__ bias2)
{
    int i = blockIdx.x * blockDim.x + threadIdx.x;
    if (i < 256) bias2[i] = 2.f * msg_b[i];
    if (i >= 256 * 256) return;
    int row = i >> 8, col = i & 255;
    wm2[i] = (row < 128) ? (msgW[row * 256 + col] + msgW[(row + 128) * 256 + col])
                         : (2.f * msgW[(row + 128) * 256 + col]);
}

// ---------------- CSR build (once per launch) ----------------
__global__ void count_deg_kernel(const int* __restrict__ from_idx, const int* __restrict__ to_idx,
                                 int* __restrict__ deg)
{
    int e = blockIdx.x * blockDim.x + threadIdx.x;
    if (e >= VE) return;
    atomicAdd(&deg[to_idx[e]], 1);
    atomicAdd(&deg[from_idx[e]], 1);
}

__global__ __launch_bounds__(256) void scan_kernel(const int* __restrict__ deg,
                                                   int* __restrict__ off, int* __restrict__ pos)
{
    __shared__ int part[256];
    int t = threadIdx.x;
    int base = t * 24;
    int local[24];
    int s = 0;
#pragma unroll
    for (int i = 0; i < 24; i++) {
        local[i] = s;
        s += deg[base + i];
    }
    part[t] = s;
    __syncthreads();
    if (t == 0) {
        int acc = 0;
        for (int i = 0; i < 256; i++) { int v = part[i]; part[i] = acc; acc += v; }
    }
    __syncthreads();
    int o = part[t];
#pragma unroll
    for (int i = 0; i < 24; i++) {
        off[base + i] = o + local[i];
        pos[base + i] = o + local[i];
    }
    if (t == 255) off[VN] = o + s;
}

__global__ void fill_csr_kernel(const int* __restrict__ from_idx, const int* __restrict__ to_idx,
                                int* __restrict__ pos, int* __restrict__ list)
{
    int e = blockIdx.x * blockDim.x + threadIdx.x;
    if (e >= VE) return;
    int i = atomicAdd(&pos[to_idx[e]], 1);
    list[i] = 2 * e;
    i = atomicAdd(&pos[from_idx[e]], 1);
    list[i] = 2 * e + 1;
}

// agg[n] = sum over incident entries: even -> fwd[e], odd -> bwd[e]
__global__ __launch_bounds__(256) void agg_gather_kernel(
    const float* __restrict__ fwd, const float* __restrict__ bwd,
    const int* __restrict__ off, const int* __restrict__ list,
    float* __restrict__ agg)
{
    int n = blockIdx.x;
    int c = threadIdx.x;
    int s0 = off[n], s1 = off[n + 1];
    float s = 0.f;
    for (int j = s0; j < s1; j++) {
        int ent = __ldg(&list[j]);
        const float* src = (ent & 1) ? bwd : fwd;
        s += src[(size_t)(ent >> 1) * 256 + c];
    }
    agg[(size_t)n * 256 + c] = s;
}

// ---------------- transport MLP: 8 rows/block (fdim -> 64 -> 64) ----------------
__global__ __launch_bounds__(64) void transport_mlp8_kernel(
    const float* __restrict__ upd, int ld, int foff, int fdim,
    const float* __restrict__ W1, const float* __restrict__ b1,
    const float* __restrict__ W2, const float* __restrict__ b2,
    float* __restrict__ tout, int maxr, int nreal)
{
    __shared__ float f[8][257];
    __shared__ float hid[8][65];
    int i0 = blockIdx.x * 8;
    int g = blockIdx.y;
    int j = threadIdx.x;

    for (int r = 0; r < 8; r++) {
        int row = i0 + r;
        if (row < nreal) {
            const float* frow = upd + ((size_t)g * nreal + row) * ld + foff;
            for (int k = j; k < fdim; k += 64) f[r][k] = frow[k];
        }
    }
    __syncthreads();

    float h[8];
#pragma unroll
    for (int r = 0; r < 8; r++) h[r] = b1[j];
    for (int k = 0; k < fdim; k++) {
        float w = W1[k * 64 + j];
#pragma unroll
        for (int r = 0; r < 8; r++) h[r] += f[r][k] * w;
    }
#pragma unroll
    for (int r = 0; r < 8; r++) hid[r][j] = fmaxf(h[r], 0.f);
    __syncthreads();

    float o[8];
#pragma unroll
    for (int r = 0; r < 8; r++) o[r] = b2[j];
    for (int k = 0; k < 64; k++) {
        float w = W2[k * 64 + j];
#pragma unroll
        for (int r = 0; r < 8; r++) o[r] += hid[r][k] * w;
    }
#pragma unroll
    for (int r = 0; r < 8; r++) {
        int row = i0 + r;
        tout[((size_t)g * maxr + row) * 64 + j] = (row < nreal) ? o[r] : 0.f;
    }
}

// ---------------- la = (tq @ tc^T) / TEMP ----------------
__global__ void la_kernel(const float* __restrict__ t, float* __restrict__ la, int maxr)
{
    __shared__ float Tq[16][65];
    __shared__ float Tc[16][65];
    int b = blockIdx.z;
    int q0 = blockIdx.y * 16;
    int c0 = blockIdx.x * 16;
    const float* tq = t + (size_t)(2 * b) * maxr * 64;
    const float* tc = t + (size_t)(2 * b + 1) * maxr * 64;
    int ty = threadIdx.y, tx = threadIdx.x;
    int lin = ty * 16 + tx;
#pragma unroll
    for (int u = 0; u < 4; u++) {
        int idx = lin + u * 256;
        int r = idx / 64, k = idx % 64;
        Tq[r][k] = tq[(size_t)(q0 + r) * 64 + k];
        Tc[r][k] = tc[(size_t)(c0 + r) * 64 + k];
    }
    __syncthreads();
    float s = 0.f;
#pragma unroll
    for (int k = 0; k < 64; k++) s += Tq[ty][k] * Tc[tx][k];
    la[((size_t)b * maxr + q0 + ty) * maxr + c0 + tx] = s * INV_TEMP;
}

// ---------------- fused node Sinkhorn: smem-resident 64x64, 10 iters + exp
__global__ __launch_bounds__(256) void node_sink_kernel(float* __restrict__ la)
{
    __shared__ float L[64][65];
    float* base = la + (size_t)blockIdx.x * 4096;
    int tid = threadIdx.x;
    for (int i = tid; i < 4096; i += 256) L[i >> 6][i & 63] = base[i];
    __syncthreads();
    int r = tid >> 2;
    int part = (tid & 3) * 16;
    for (int iter = 0; iter < SINK_ITERS; iter++) {
        {
            float m = -INFINITY;
#pragma unroll
            for (int i = 0; i < 16; i++) m = fmaxf(m, L[r][part + i]);
            m = fmaxf(m, __shfl_xor_sync(0xFFFFFFFFu, m, 1));
            m = fmaxf(m, __shfl_xor_sync(0xFFFFFFFFu, m, 2));
            float s = 0.f;
#pragma unroll
            for (int i = 0; i < 16; i++) s += expf(L[r][part + i] - m);
            s += __shfl_xor_sync(0xFFFFFFFFu, s, 1);
            s += __shfl_xor_sync(0xFFFFFFFFu, s, 2);
            float lse = m + logf(s);
#pragma unroll
            for (int i = 0; i < 16; i++) L[r][part + i] -= lse;
        }
        __syncthreads();
        {
            float m = -INFINITY;
#pragma unroll
            for (int i = 0; i < 16; i++) m = fmaxf(m, L[part + i][r]);
            m = fmaxf(m, __shfl_xor_sync(0xFFFFFFFFu, m, 1));
            m = fmaxf(m, __shfl_xor_sync(0xFFFFFFFFu, m, 2));
            float s = 0.f;
#pragma unroll
            for (int i = 0; i < 16; i++) s += expf(L[part + i][r] - m);
            s += __shfl_xor_sync(0xFFFFFFFFu, s, 1);
            s += __shfl_xor_sync(0xFFFFFFFFu, s, 2);
            float lse = m + logf(s);
#pragma unroll
            for (int i = 0; i < 16; i++) L[part + i][r] -= lse;
        }
        __syncthreads();
    }
    for (int i = tid; i < 4096; i += 256) base[i] = expf(L[i >> 6][i & 63]);
}

// ---------------- fused edge Sinkhorn: 256x256, 10 iters + exp
__global__ __launch_bounds__(1024) void edge_sink_kernel(float* __restrict__ la)
{
    float* base = la + (size_t)blockIdx.x * 65536;
    int tid = threadIdx.x;
    int wid = tid >> 5, lane = tid & 31;
    __shared__ float cr[4][256];
    int c = tid & 255, g = tid >> 8;
    for (int iter = 0; iter < SINK_ITERS; iter++) {
        for (int r = wid; r < 256; r += 32) {
            float* rp = base + (size_t)r * 256;
            float4 v0 = *(float4*)(rp + lane * 4);
            float4 v1 = *(float4*)(rp + 128 + lane * 4);
            float m = fmaxf(fmaxf(fmaxf(v0.x, v0.y), fmaxf(v0.z, v0.w)),
                            fmaxf(fmaxf(v1.x, v1.y), fmaxf(v1.z, v1.w)));
#pragma unroll
            for (int o = 16; o > 0; o >>= 1) m = fmaxf(m, __shfl_xor_sync(0xFFFFFFFFu, m, o));
            float s = expf(v0.x - m) + expf(v0.y - m) + expf(v0.z - m) + expf(v0.w - m)
                    + expf(v1.x - m) + expf(v1.y - m) + expf(v1.z - m) + expf(v1.w - m);
#pragma unroll
            for (int o = 16; o > 0; o >>= 1) s += __shfl_xor_sync(0xFFFFFFFFu, s, o);
            float lse = m + logf(s);
            v0.x -= lse; v0.y -= lse; v0.z -= lse; v0.w -= lse;
            v1.x -= lse; v1.y -= lse; v1.z -= lse; v1.w -= lse;
            *(float4*)(rp + lane * 4) = v0;
            *(float4*)(rp + 128 + lane * 4) = v1;
        }
        __syncthreads();
        float m = -INFINITY;
        for (int r = g * 64; r < g * 64 + 64; r++) m = fmaxf(m, base[(size_t)r * 256 + c]);
        cr[g][c] = m;
        __syncthreads();
        if (g == 0) cr[0][c] = fmaxf(fmaxf(cr[0][c], cr[1][c]), fmaxf(cr[2][c], cr[3][c]));
        __syncthreads();
        m = cr[0][c];
        float s = 0.f;
        for (int r = g * 64; r < g * 64 + 64; r++) s += expf(base[(size_t)r * 256 + c] - m);
        __syncthreads();
        cr[g][c] = s;
        __syncthreads();
        if (g == 0) cr[0][c] = m + logf(cr[0][c] + cr[1][c] + cr[2][c] + cr[3][c]);
        __syncthreads();
        float lse = cr[0][c];
        bool last = (iter == SINK_ITERS - 1);
        for (int r = g * 64; r < g * 64 + 64; r++) {
            float v = base[(size_t)r * 256 + c] - lse;
            base[(size_t)r * 256 + c] = last ? expf(v) : v;
        }
        __syncthreads();
    }
}

// ---------------- score ----------------
__global__ void score_kernel(const float* __restrict__ upd_node, const float* __restrict__ plan,
                             float* __restrict__ out)
{
    int b = blockIdx.x;
    int t = threadIdx.x;
    __shared__ float P[64][64];
    __shared__ float FC[48][128];
    __shared__ float red[128];
    for (int idx = t; idx < 64 * 64; idx += 128)
        P[idx / 64][idx % 64] = plan[(size_t)b * 4096 + idx];
    for (int idx = t; idx < 48 * 128; idx += 128) {
        int c = idx / 128, d = idx % 128;
        FC[c][d] = upd_node[((size_t)(2 * b + 1) * 48 + c) * 768 + 640 + d];
    }
    __syncthreads();
    float acc = 0.f;
    for (int q = 0; q < 64; q++) {
        float s = 0.f;
#pragma unroll 8
        for (int c = 0; c < 48; c++) s += P[q][c] * FC[c][t];
        float fq = 0.f;
        if (q < 48) fq = upd_node[((size_t)(2 * b) * 48 + q) * 768 + 640 + t];
        acc += fmaxf(fq - s, 0.f);
    }
    red[t] = acc;
    __syncthreads();
    for (int s2 = 64; s2 > 0; s2 >>= 1) {
        if (t < s2) red[t] += red[t + s2];
        __syncthreads();
    }
    if (t == 0) out[b] = -red[0];
}

// ---------------- host helpers ----------------
struct Seg { const float* A; int lda; const int* rows; };

static void bgemmE(Seg s0, const int* s0sum, Seg s1, Seg s2, int kb1, int kb2,
                   const float* B, const float* bias,
                   float* C, float* Cd, int ldc, int M, int N, int K, int relu, int dual)
{
    dim3 g(N / 128, M / 128, dual ? 2 : 1);
    bgemm_kernel<128><<<g, 256>>>(s0.A, s0.lda, s0.rows, s0sum,
                                  s1.A, s1.lda, s1.rows, s2.A, s2.lda, kb1, kb2,
                                  B, bias, C, Cd, ldc, N, K, relu);
}

static void bgemmN(Seg s0, Seg s1, int kb1, const float* B, const float* bias,
                   float* C, int ldc, int M, int N, int K, int relu)
{
    dim3 g(N / 128, M / 64, 1);
    bgemm_kernel<64><<<g, 256>>>(s0.A, s0.lda, s0.rows, nullptr,
                                 s1.A, s1.lda, s1.rows, nullptr, 0, kb1, K,
                                 B, bias, C, nullptr, ldc, N, K, relu);
}

static void zero_buf(float* p, size_t n)
{
    int grid = (int)((n + 255) / 256);
    if (grid > 8192) grid = 8192;
    zero_kernel<<<grid, 256>>>(p, n);
}

extern "C" void kernel_launch(void* const* d_in, const int* in_sizes, int n_in,
                              void* d_out, int out_size)
{
    const float* node_features = (const float*)d_in[0];
    const float* edge_features = (const float*)d_in[1];
    const int* from_idx = (const int*)d_in[2];
    const int* to_idx = (const int*)d_in[3];
    const float* enc_node_W = (const float*)d_in[4];
    const float* enc_node_b = (const float*)d_in[5];
    const float* enc_edge_W = (const float*)d_in[6];
    const float* enc_edge_b = (const float*)d_in[7];
    const float* ni_W1 = (const float*)d_in[8];
    const float* ni_b1 = (const float*)d_in[9];
    const float* ni_W2 = (const float*)d_in[10];
    const float* ni_b2 = (const float*)d_in[11];
    const float* ei_W1 = (const float*)d_in[12];
    const float* ei_b1 = (const float*)d_in[13];
    const float* ei_W2 = (const float*)d_in[14];
    const float* ei_b2 = (const float*)d_in[15];
    const float* msg_W = (const float*)d_in[16];
    const float* msg_b = (const float*)d_in[17];
    const float* nu_W1 = (const float*)d_in[18];
    const float* nu_b1 = (const float*)d_in[19];
    const float* nu_W2 = (const float*)d_in[20];
    const float* nu_b2 = (const float*)d_in[21];
    const float* ns_W1 = (const float*)d_in[22];
    const float* ns_b1 = (const float*)d_in[23];
    const float* ns_W2 = (const float*)d_in[24];
    const float* ns_b2 = (const float*)d_in[25];
    const float* es_W1 = (const float*)d_in[26];
    const float* es_b1 = (const float*)d_in[27];
    const float* es_W2 = (const float*)d_in[28];
    const float* es_b2 = (const float*)d_in[29];

    float* S = nullptr;
    cudaGetSymbolAddress((void**)&S, g_scratch);

    float* enc_n = S + OFF_ENC_N;
    float* enc_e = S + OFF_ENC_E;
    float* node_store = S + OFF_NS;
    float* edge_store = S + OFF_ES;
    float* UN = S + OFF_UN;
    float* UE = S + OFF_UE;
    float* tmpN = S + OFF_TMPN;
    float* tmpE = S + OFF_TMPE;
    float* hcomb = S + OFF_HC;
    float* ecomb = S + OFF_EC;
    float* fwd = S + OFF_FWD;
    float* bwd = S + OFF_BWD;
    float* agg = S + OFF_AGG;
    float* TN = S + OFF_TN;
    float* TE = S + OFF_TE;
    float* PLN = S + OFF_PLN;
    float* PLE = S + OFF_PLE;
    float* wm2 = S + OFF_WM2;
    float* bias2 = wm2 + 256 * 256;
    int* csr = (int*)(S + OFF_CSR);
    int* deg = csr;                 // VN
    int* off = csr + VN;            // VN+1
    int* pos = off + VN + 1;        // VN
    int* list = pos + VN;           // 2*VE

    Seg none{nullptr, 0, nullptr};

    // one-time zeroing + precompute
    zero_buf(node_store, SZ_NS);
    zero_buf(edge_store, SZ_ES);
    zero_buf((float*)deg, VN);
    wm2f_kernel<<<(256 * 256 + 255) / 256, 256>>>(msg_W, wm2, msg_b, bias2);
    count_deg_kernel<<<(VE + 255) / 256, 256>>>(from_idx, to_idx, deg);
    scan_kernel<<<1, 256>>>(deg, off, pos);
    fill_csr_kernel<<<(VE + 255) / 256, 256>>>(from_idx, to_idx, pos, list);

    // encoders (K=32)
    bgemmN(Seg{node_features, DIN, nullptr}, none, 32,
           enc_node_W, enc_node_b, enc_n, 128, VN, 128, 32, 0);
    bgemmE(Seg{edge_features, DIN, nullptr}, nullptr, none, none, 32, 32,
           enc_edge_W, enc_edge_b, enc_e, nullptr, 128, VE, 128, 32, 0, 0);

    for (int k = 0; k < KK; k++) {
        for (int p = 1; p <= TT; p++) {
            const float* hptr = (p == 1) ? enc_n : (UN + (size_t)(p - 1) * 128);
            int hlda = (p == 1) ? 128 : 768;

            // h_comb = mlp2([h | node_store slice], ni)
            bgemmN(Seg{hptr, hlda, nullptr},
                   Seg{node_store + (size_t)(p - 1) * 128, 768, nullptr}, 128,
                   ni_W1, ni_b1, tmpN, 256, VN, 256, 256, 1);
            bgemmN(Seg{tmpN, 256, nullptr}, none, 256,
                   ni_W2, ni_b2, hcomb, 128, VN, 128, 256, 0);

            // e_comb = mlp2([enc_e | edge_store slice], ei)
            bgemmE(Seg{enc_e, 128, nullptr}, nullptr,
                   Seg{edge_store + (size_t)(p - 1) * 256, 1536, nullptr}, none, 128, 384,
                   ei_W1, ei_b1, tmpE, nullptr, 384, VE, 384, 384, 1, 0);
            bgemmE(Seg{tmpE, 384, nullptr}, nullptr, none, none, 384, 384,
                   ei_W2, ei_b2, ecomb, nullptr, 128, VE, 128, 384, 0, 0);

            // fwd & bwd in ONE dual 3-seg launch:
            //   fwd = [h_comb[from] | h_comb[to] | ecomb] @ msg_W + msg_b
            bgemmE(Seg{hcomb, 128, from_idx}, nullptr, Seg{hcomb, 128, to_idx},
                   Seg{ecomb, 128, nullptr}, 128, 256,
                   msg_W, msg_b, fwd, bwd, 256, VE, 256, 384, 0, 1);

            // aggregate via CSR gather (no atomics)
            agg_gather_kernel<<<VN, 256>>>(fwd, bwd, off, list, agg);

            // h_new = mlp2([h_comb | agg], nu) -> UN slot p
            bgemmN(Seg{hcomb, 128, nullptr}, Seg{agg, 256, nullptr}, 128,
                   nu_W1, nu_b1, tmpN, 256, VN, 256, 384, 1);
            bgemmN(Seg{tmpN, 256, nullptr}, none, 256,
                   nu_W2, nu_b2, UN + (size_t)p * 128, 768, VN, 128, 256, 0);

            // msgs2 = [(h[from]+h[to]) | ecomb] @ [Wa+Wb; 2Wc] + 2*msg_b -> UE slot p
            // sum-gather fused into the GEMM A-tile fill (seg0, r0b=to_idx).
            bgemmE(Seg{UN + (size_t)p * 128, 768, from_idx}, to_idx,
                   Seg{ecomb, 128, nullptr}, none, 128, 256,
                   wm2, bias2, UE + (size_t)p * 256, nullptr, 1536, VE, 256, 256, 0, 0);
        }

        // ----- node transport -----
        transport_mlp8_kernel<<<dim3(MAXN / 8, NGRP), 64>>>(UN, 768, 640, 128, ns_W1, ns_b1,
                                                            ns_W2, ns_b2, TN, MAXN, NPER);
        la_kernel<<<dim3(4, 4, BNUM), dim3(16, 16)>>>(TN, PLN, MAXN);
        node_sink_kernel<<<BNUM, 256>>>(PLN);
        trans_apply_mma<<<dim3(5, 1, NGRP), 256>>>(PLN, UN, node_store, MAXN, NPER, 768, 128, 64);

        // ----- edge transport -----
        transport_mlp8_kernel<<<dim3(MAXE / 8, NGRP), 64>>>(UE, 1536, 1280, 256, es_W1, es_b1,
                                                            es_W2, es_b2, TE, MAXE, EPER);
        la_kernel<<<dim3(16, 16, BNUM), dim3(16, 16)>>>(TE, PLE, MAXE);
        edge_sink_kernel<<<BNUM, 1024>>>(PLE);
        trans_apply_mma<<<dim3(10, 3, NGRP), 256>>>(PLE, UE, edge_store, MAXE, EPER, 1536, 256, 192);
    }

    // ----- score -----
    score_kernel<<<BNUM, 128>>>(UN, PLN, (float*)d_out);
}

// round 16
// speedup vs baseline: 1.1530x; 1.1530x over previous
#include <cuda_runtime.h>
#include <cuda_bf16.h>
#include <math.h>
#include <stdint.h>

// ---------------- constants ----------------
#define BNUM 64
#define NGRP 128
#define NPER 48
#define EPER 192
#define MAXN 64
#define MAXE 256
#define DIN 32
#define TT 5
#define KK 3
#define VN 6144
#define VE 24576
#define INV_TEMP 10.0f
#define SINK_ITERS 10

// ---------------- scratch layout (floats) ----------------
#define SZ_ENC_N ((size_t)VN * 128)
#define SZ_ENC_E ((size_t)VE * 128)
#define SZ_NS ((size_t)VN * 768)
#define SZ_ES ((size_t)VE * 1536)
#define SZ_UN ((size_t)VN * 768)
#define SZ_UE ((size_t)VE * 1536)
#define SZ_TMPN ((size_t)VN * 256)
#define SZ_TMPE ((size_t)VE * 384)
#define SZ_HC ((size_t)VN * 128)
#define SZ_EC ((size_t)VE * 128)
#define SZ_FWD ((size_t)VE * 256)
#define SZ_AGG ((size_t)VN * 256)
#define SZ_TN ((size_t)NGRP * 64 * 64)
#define SZ_TE ((size_t)NGRP * 256 * 64)
#define SZ_PLN ((size_t)BNUM * 64 * 64)
#define SZ_PLE ((size_t)BNUM * 256 * 256)
#define SZ_EWC ((size_t)VE * 256)
#define SZ_WAB ((size_t)128 * 256)
#define SZ_CSR ((size_t)(3 * VN + 2 + 2 * VE))

#define OFF_ENC_N ((size_t)0)
#define OFF_ENC_E (OFF_ENC_N + SZ_ENC_N)
#define OFF_NS (OFF_ENC_E + SZ_ENC_E)
#define OFF_ES (OFF_NS + SZ_NS)
#define OFF_UN (OFF_ES + SZ_ES)
#define OFF_UE (OFF_UN + SZ_UN)
#define OFF_TMPN (OFF_UE + SZ_UE)
#define OFF_TMPE (OFF_TMPN + SZ_TMPN)
#define OFF_HC (OFF_TMPE + SZ_TMPE)
#define OFF_EC (OFF_HC + SZ_HC)
#define OFF_FWD (OFF_EC + SZ_EC)
#define OFF_BWD (OFF_FWD + SZ_FWD)
#define OFF_AGG (OFF_BWD + SZ_FWD)
#define OFF_TN (OFF_AGG + SZ_AGG)
#define OFF_TE (OFF_TN + SZ_TN)
#define OFF_PLN (OFF_TE + SZ_TE)
#define OFF_PLE (OFF_PLN + SZ_PLN)
#define OFF_EWC (OFF_PLE + SZ_PLE)
#define OFF_WAB (OFF_EWC + SZ_EWC)
#define OFF_CSR (OFF_WAB + SZ_WAB)
#define SCRATCH_TOTAL (OFF_CSR + SZ_CSR)

__device__ __align__(256) float g_scratch[SCRATCH_TOTAL];

// ---------------- mma helpers ----------------
__device__ __forceinline__ uint32_t s2u(const void* p) {
    return (uint32_t)__cvta_generic_to_shared(p);
}

#define LDSM4(r0, r1, r2, r3, addr) \
    asm volatile("ldmatrix.sync.aligned.m8n8.x4.shared.b16 {%0,%1,%2,%3},[%4];" \
                 : "=r"(r0), "=r"(r1), "=r"(r2), "=r"(r3) : "r"(addr))

#define LDSM4T(r0, r1, r2, r3, addr) \
    asm volatile("ldmatrix.sync.aligned.m8n8.x4.trans.shared.b16 {%0,%1,%2,%3},[%4];" \
                 : "=r"(r0), "=r"(r1), "=r"(r2), "=r"(r3) : "r"(addr))

#define MMA16816(c, a, b0, b1) \
    asm volatile("mma.sync.aligned.m16n8k16.row.col.f32.bf16.bf16.f32 " \
                 "{%0,%1,%2,%3},{%4,%5,%6,%7},{%8,%9},{%0,%1,%2,%3};" \
                 : "+f"((c)[0]), "+f"((c)[1]), "+f"((c)[2]), "+f"((c)[3]) \
                 : "r"((a)[0]), "r"((a)[1]), "r"((a)[2]), "r"((a)[3]), "r"(b0), "r"(b1))

__device__ __forceinline__ void split_store4(__nv_bfloat16* ph, __nv_bfloat16* pm, float4 v)
{
    __nv_bfloat16 h0 = __float2bfloat16(v.x);
    __nv_bfloat16 h1 = __float2bfloat16(v.y);
    __nv_bfloat16 h2 = __float2bfloat16(v.z);
    __nv_bfloat16 h3 = __float2bfloat16(v.w);
    ((__nv_bfloat162*)ph)[0] = __nv_bfloat162(h0, h1);
    ((__nv_bfloat162*)ph)[1] = __nv_bfloat162(h2, h3);
    ((__nv_bfloat162*)pm)[0] = __nv_bfloat162(__float2bfloat16(v.x - __bfloat162float(h0)),
                                              __float2bfloat16(v.y - __bfloat162float(h1)));
    ((__nv_bfloat162*)pm)[1] = __nv_bfloat162(__float2bfloat16(v.z - __bfloat162float(h2)),
                                              __float2bfloat16(v.w - __bfloat162float(h3)));
}

// =====================================================================
// bgemm<BM>: tensor-core GEMM, 2-term bf16 split (hi*hi + hi*mid + mid*hi).
// C[M,N] = concat_K(A0|A1) @ B + bias + cs*Cin, optional relu.
// BM=128: 8 warps 4x2 (warp 32x64). BM=64: 8 warps 2x4 (warp 32x32).
// Dual mode (gridDim.z==2): z==1 swaps gathers, writes C_dual.
// M%BM==0, N%128==0, K%32==0, kb1%32==0, ldb==N, 16B alignment.
// =====================================================================
template <int BM>
__global__ __launch_bounds__(256, 2) void bgemm_kernel(
    const float* __restrict__ A0, int lda0, const int* __restrict__ r0a,
    const float* __restrict__ A1, int lda1, const int* __restrict__ r1a,
    int kb1,
    const float* __restrict__ B,
    const float* __restrict__ bias,
    const float* __restrict__ Cin, int ldcin, float cs,
    float* __restrict__ C, float* __restrict__ C_dual, int ldc,
    int Ndim, int Kdim, int relu)
{
    constexpr int WN = (BM == 128) ? 2 : 4;
    constexpr int CP = 128 / WN;
    constexpr int NP = CP / 16;

    __shared__ __align__(16) __nv_bfloat16 Ah[BM][40];
    __shared__ __align__(16) __nv_bfloat16 Am[BM][40];
    __shared__ __align__(16) __nv_bfloat16 Bh[32][136];
    __shared__ __align__(16) __nv_bfloat16 Bm[32][136];
    __shared__ int rows0[BM], rows1[BM];

    const int tid = threadIdx.x;
    const int lane = tid & 31;
    const int wid = tid >> 5;
    const int warp_m = wid / WN;
    const int warp_n = wid % WN;
    const int row0 = blockIdx.y * BM;
    const int col0 = blockIdx.x * 128;

    const int* g0 = r0a;
    const int* g1 = r1a;
    float* Cout = C;
    if (blockIdx.z == 1) { g0 = r1a; g1 = r0a; Cout = C_dual; }

    if (tid < BM) {
        rows0[tid] = g0 ? __ldg(&g0[row0 + tid]) : (row0 + tid);
        rows1[tid] = g1 ? __ldg(&g1[row0 + tid]) : (row0 + tid);
    }
    __syncthreads();

    float acc[2][NP * 2][4];
#pragma unroll
    for (int i = 0; i < 2; i++)
#pragma unroll
        for (int j = 0; j < NP * 2; j++)
#pragma unroll
            for (int l = 0; l < 4; l++) acc[i][j][l] = 0.f;

    for (int k0 = 0; k0 < Kdim; k0 += 32) {
        const float* Ap; int lda; const int* rs; int kloc;
        if (k0 < kb1) { Ap = A0; lda = lda0; rs = rows0; kloc = k0; }
        else { Ap = A1; lda = lda1; rs = rows1; kloc = k0 - kb1; }

#pragma unroll
        for (int u = 0; u < BM / 32; u++) {
            int idx = tid + u * 256;
            int m = idx >> 3;
            int kq = (idx & 7) << 2;
            float4 v = *(const float4*)(Ap + (size_t)rs[m] * lda + kloc + kq);
            split_store4(&Ah[m][kq], &Am[m][kq], v);
        }
#pragma unroll
        for (int u = 0; u < 4; u++) {
            int idx = tid + u * 256;
            int kk = idx >> 5;
            int nq = (idx & 31) << 2;
            float4 v = *(const float4*)(B + (size_t)(k0 + kk) * Ndim + col0 + nq);
            split_store4(&Bh[kk][nq], &Bm[kk][nq], v);
        }
        __syncthreads();

#pragma unroll
        for (int h = 0; h < 2; h++) {
            const int kh = h * 16;
            uint32_t ah[2][4], am[2][4];
#pragma unroll
            for (int mt = 0; mt < 2; mt++) {
                int r = warp_m * 32 + mt * 16 + (lane & 15);
                int kc = kh + ((lane >> 4) << 3);
                uint32_t addr = s2u(&Ah[r][kc]);
                LDSM4(ah[mt][0], ah[mt][1], ah[mt][2], ah[mt][3], addr);
                addr = s2u(&Am[r][kc]);
                LDSM4(am[mt][0], am[mt][1], am[mt][2], am[mt][3], addr);
            }
#pragma unroll
            for (int p = 0; p < NP; p++) {
                uint32_t bh[4], bm[4];
                int kr = kh + (lane & 15);
                int cb = warp_n * CP + p * 16 + ((lane >> 4) << 3);
                uint32_t addr = s2u(&Bh[kr][cb]);
                LDSM4T(bh[0], bh[1], bh[2], bh[3], addr);
                addr = s2u(&Bm[kr][cb]);
                LDSM4T(bm[0], bm[1], bm[2], bm[3], addr);
#pragma unroll
                for (int mt = 0; mt < 2; mt++) {
                    MMA16816(acc[mt][p * 2 + 0], ah[mt], bh[0], bh[1]);
                    MMA16816(acc[mt][p * 2 + 0], ah[mt], bm[0], bm[1]);
                    MMA16816(acc[mt][p * 2 + 0], am[mt], bh[0], bh[1]);
                    MMA16816(acc[mt][p * 2 + 1], ah[mt], bh[2], bh[3]);
                    MMA16816(acc[mt][p * 2 + 1], ah[mt], bm[2], bm[3]);
                    MMA16816(acc[mt][p * 2 + 1], am[mt], bh[2], bh[3]);
                }
            }
        }
        __syncthreads();
    }

    const int rbase = row0 + warp_m * 32 + (lane >> 2);
    const int cbase = col0 + warp_n * CP + (lane & 3) * 2;
#pragma unroll
    for (int mt = 0; mt < 2; mt++) {
#pragma unroll
        for (int hf = 0; hf < 2; hf++) {
            int r = rbase + mt * 16 + hf * 8;
            float* crow = Cout + (size_t)r * ldc;
            const float* cinr = Cin ? (Cin + (size_t)r * ldcin) : nullptr;
#pragma unroll
            for (int nt = 0; nt < NP * 2; nt++) {
                int c = cbase + nt * 8;
                float v0 = acc[mt][nt][hf * 2 + 0];
                float v1 = acc[mt][nt][hf * 2 + 1];
                if (bias) { v0 += __ldg(&bias[c]); v1 += __ldg(&bias[c + 1]); }
                if (cinr) { v0 += cs * cinr[c]; v1 += cs * cinr[c + 1]; }
                if (relu) { v0 = fmaxf(v0, 0.f); v1 = fmaxf(v1, 0.f); }
                crow[c] = v0;
                crow[c + 1] = v1;
            }
        }
    }
}

// =====================================================================
// trans_apply_mma: store rows = plan(^T) @ feats, bf16-split tensor cores.
// =====================================================================
__global__ __launch_bounds__(256) void trans_apply_mma(
    const float* __restrict__ plan, const float* __restrict__ upd,
    float* __restrict__ store, int maxr, int nreal, int ld, int coff, int padK)
{
    __shared__ __align__(16) __nv_bfloat16 Ah[64][40];
    __shared__ __align__(16) __nv_bfloat16 Am[64][40];
    __shared__ __align__(16) __nv_bfloat16 Bh[32][136];
    __shared__ __align__(16) __nv_bfloat16 Bm[32][136];

    const int tid = threadIdx.x;
    const int lane = tid & 31;
    const int wid = tid >> 5;
    const int warp_m = wid >> 2;
    const int warp_n = wid & 3;
    const int z = blockIdx.z;
    const int b = z >> 1;
    const int mode = z & 1;
    const float* P = plan + (size_t)b * maxr * maxr;
    const int fgrp = 2 * b + (mode ? 0 : 1);
    const int ogrp = 2 * b + mode;
    const float* F = upd + (size_t)fgrp * nreal * ld + coff;
    float* C = store + (size_t)ogrp * nreal * ld + coff;
    const int row0 = blockIdx.y * 64;
    const int col0 = blockIdx.x * 128;

    float acc[2][4][4];
#pragma unroll
    for (int i = 0; i < 2; i++)
#pragma unroll
        for (int j = 0; j < 4; j++)
#pragma unroll
            for (int l = 0; l < 4; l++) acc[i][j][l] = 0.f;

    for (int k0 = 0; k0 < padK; k0 += 32) {
        if (mode == 0) {
#pragma unroll
            for (int u = 0; u < 2; u++) {
                int idx = tid + u * 256;
                int r = idx >> 3;
                int kq = (idx & 7) << 2;
                float4 v = *(const float4*)(P + (size_t)(row0 + r) * maxr + k0 + kq);
                split_store4(&Ah[r][kq], &Am[r][kq], v);
            }
        } else {
#pragma unroll
            for (int u = 0; u < 8; u++) {
                int idx = tid + u * 256;
                int r = idx & 63;
                int kk = idx >> 6;
                float v = P[(size_t)(k0 + kk) * maxr + row0 + r];
                __nv_bfloat16 h = __float2bfloat16(v);
                Ah[r][kk] = h;
                Am[r][kk] = __float2bfloat16(v - __bfloat162float(h));
            }
        }
#pragma unroll
        for (int u = 0; u < 4; u++) {
            int idx = tid + u * 256;
            int kk = idx >> 5;
            int nq = (idx & 31) << 2;
            int gk = k0 + kk;
            float4 v = make_float4(0.f, 0.f, 0.f, 0.f);
            if (gk < nreal) v = *(const float4*)(F + (size_t)gk * ld + col0 + nq);
            split_store4(&Bh[kk][nq], &Bm[kk][nq], v);
        }
        __syncthreads();

#pragma unroll
        for (int h = 0; h < 2; h++) {
            const int kh = h * 16;
            uint32_t ah[2][4], am[2][4];
#pragma unroll
            for (int mt = 0; mt < 2; mt++) {
                int r = warp_m * 32 + mt * 16 + (lane & 15);
                int kc = kh + ((lane >> 4) << 3);
                uint32_t addr = s2u(&Ah[r][kc]);
                LDSM4(ah[mt][0], ah[mt][1], ah[mt][2], ah[mt][3], addr);
                addr = s2u(&Am[r][kc]);
                LDSM4(am[mt][0], am[mt][1], am[mt][2], am[mt][3], addr);
            }
#pragma unroll
            for (int p = 0; p < 2; p++) {
                uint32_t bh[4], bm[4];
                int kr = kh + (lane & 15);
                int cb = warp_n * 32 + p * 16 + ((lane >> 4) << 3);
                uint32_t addr = s2u(&Bh[kr][cb]);
                LDSM4T(bh[0], bh[1], bh[2], bh[3], addr);
                addr = s2u(&Bm[kr][cb]);
                LDSM4T(bm[0], bm[1], bm[2], bm[3], addr);
#pragma unroll
                for (int mt = 0; mt < 2; mt++) {
                    MMA16816(acc[mt][p * 2 + 0], ah[mt], bh[0], bh[1]);
                    MMA16816(acc[mt][p * 2 + 0], ah[mt], bm[0], bm[1]);
                    MMA16816(acc[mt][p * 2 + 0], am[mt], bh[0], bh[1]);
                    MMA16816(acc[mt][p * 2 + 1], ah[mt], bh[2], bh[3]);
                    MMA16816(acc[mt][p * 2 + 1], ah[mt], bm[2], bm[3]);
                    MMA16816(acc[mt][p * 2 + 1], am[mt], bh[2], bh[3]);
                }
            }
        }
        __syncthreads();
    }

    const int rbase = row0 + warp_m * 32 + (lane >> 2);
    const int cbase = col0 + warp_n * 32 + (lane & 3) * 2;
#pragma unroll
    for (int mt = 0; mt < 2; mt++) {
#pragma unroll
        for (int hf = 0; hf < 2; hf++) {
            int r = rbase + mt * 16 + hf * 8;
            if (r >= nreal) continue;
            float* crow = C + (size_t)r * ld;
#pragma unroll
            for (int nt = 0; nt < 4; nt++) {
                int c = cbase + nt * 8;
                crow[c] = acc[mt][nt][hf * 2 + 0];
                crow[c + 1] = acc[mt][nt][hf * 2 + 1];
            }
        }
    }
}

// ---------------- misc elementwise ----------------
__global__ void zero_kernel(float* __restrict__ p, size_t n) {
    size_t i = (size_t)blockIdx.x * blockDim.x + threadIdx.x;
    size_t stride = (size_t)gridDim.x * blockDim.x;
    for (; i < n; i += stride) p[i] = 0.f;
}

__global__ void wab_kernel(const float* __restrict__ msgW, float* __restrict__ wab) {
    int i = blockIdx.x * blockDim.x + threadIdx.x;
    if (i < 128 * 256) wab[i] = msgW[i] + msgW[128 * 256 + i];
}

// sumsd[e][0:128] = hn[from[e]] + hn[to[e]]  (hn stride 768), float4
__global__ void sumsd_kernel(const float* __restrict__ hn, const int* __restrict__ from_idx,
                             const int* __restrict__ to_idx, float* __restrict__ out)
{
    int i = blockIdx.x * blockDim.x + threadIdx.x;
    if (i >= VE * 32) return;
    int e = i >> 5;
    int c4 = (i & 31) << 2;
    const float4 a = *(const float4*)(hn + (size_t)from_idx[e] * 768 + c4);
    const float4 b = *(const float4*)(hn + (size_t)to_idx[e] * 768 + c4);
    float4 o;
    o.x = a.x + b.x; o.y = a.y + b.y; o.z = a.z + b.z; o.w = a.w + b.w;
    *(float4*)(out + (size_t)e * 128 + c4) = o;
}

// ---------------- CSR build (once per launch) ----------------
__global__ void count_deg_kernel(const int* __restrict__ from_idx, const int* __restrict__ to_idx,
                                 int* __restrict__ deg)
{
    int e = blockIdx.x * blockDim.x + threadIdx.x;
    if (e >= VE) return;
    atomicAdd(&deg[to_idx[e]], 1);
    atomicAdd(&deg[from_idx[e]], 1);
}

__global__ __launch_bounds__(256) void scan_kernel(const int* __restrict__ deg,
                                                   int* __restrict__ off, int* __restrict__ pos)
{
    __shared__ int part[256];
    int t = threadIdx.x;
    int base = t * 24;
    int local[24];
    int s = 0;
#pragma unroll
    for (int i = 0; i < 24; i++) { local[i] = s; s += deg[base + i]; }
    part[t] = s;
    __syncthreads();
    if (t == 0) {
        int acc = 0;
        for (int i = 0; i < 256; i++) { int v = part[i]; part[i] = acc; acc += v; }
    }
    __syncthreads();
    int o = part[t];
#pragma unroll
    for (int i = 0; i < 24; i++) {
        off[base + i] = o + local[i];
        pos[base + i] = o + local[i];
    }
    if (t == 255) off[VN] = o + s;
}

__global__ void fill_csr_kernel(const int* __restrict__ from_idx, const int* __restrict__ to_idx,
                                int* __restrict__ pos, int* __restrict__ list)
{
    int e = blockIdx.x * blockDim.x + threadIdx.x;
    if (e >= VE) return;
    int i = atomicAdd(&pos[to_idx[e]], 1);
    list[i] = 2 * e;
    i = atomicAdd(&pos[from_idx[e]], 1);
    list[i] = 2 * e + 1;
}

// agg[n] = sum over incident entries: even -> fwd[e], odd -> bwd[e]
__global__ __launch_bounds__(256) void agg_gather_kernel(
    const float* __restrict__ fwd, const float* __restrict__ bwd,
    const int* __restrict__ off, const int* __restrict__ list,
    float* __restrict__ agg)
{
    int n = blockIdx.x;
    int c = threadIdx.x;
    int s0 = off[n], s1 = off[n + 1];
    float s = 0.f;
    for (int j = s0; j < s1; j++) {
        int ent = __ldg(&list[j]);
        const float* src = (ent & 1) ? bwd : fwd;
        s += src[(size_t)(ent >> 1) * 256 + c];
    }
    agg[(size_t)n * 256 + c] = s;
}

// ---------------- transport MLP: 8 rows/block (fdim -> 64 -> 64) ----------------
__global__ __launch_bounds__(64) void transport_mlp8_kernel(
    const float* __restrict__ upd, int ld, int foff, int fdim,
    const float* __restrict__ W1, const float* __restrict__ b1,
    const float* __restrict__ W2, const float* __restrict__ b2,
    float* __restrict__ tout, int maxr, int nreal)
{
    __shared__ float f[8][257];
    __shared__ float hid[8][65];
    int i0 = blockIdx.x * 8;
    int g = blockIdx.y;
    int j = threadIdx.x;

    for (int r = 0; r < 8; r++) {
        int row = i0 + r;
        if (row < nreal) {
            const float* frow = upd + ((size_t)g * nreal + row) * ld + foff;
            for (int k = j; k < fdim; k += 64) f[r][k] = frow[k];
        }
    }
    __syncthreads();

    float h[8];
#pragma unroll
    for (int r = 0; r < 8; r++) h[r] = b1[j];
    for (int k = 0; k < fdim; k++) {
        float w = W1[k * 64 + j];
#pragma unroll
        for (int r = 0; r < 8; r++) h[r] += f[r][k] * w;
    }
#pragma unroll
    for (int r = 0; r < 8; r++) hid[r][j] = fmaxf(h[r], 0.f);
    __syncthreads();

    float o[8];
#pragma unroll
    for (int r = 0; r < 8; r++) o[r] = b2[j];
    for (int k = 0; k < 64; k++) {
        float w = W2[k * 64 + j];
#pragma unroll
        for (int r = 0; r < 8; r++) o[r] += hid[r][k] * w;
    }
#pragma unroll
    for (int r = 0; r < 8; r++) {
        int row = i0 + r;
        tout[((size_t)g * maxr + row) * 64 + j] = (row < nreal) ? o[r] : 0.f;
    }
}

// ---------------- la = (tq @ tc^T) / TEMP ----------------
__global__ void la_kernel(const float* __restrict__ t, float* __restrict__ la, int maxr)
{
    __shared__ float Tq[16][65];
    __shared__ float Tc[16][65];
    int b = blockIdx.z;
    int q0 = blockIdx.y * 16;
    int c0 = blockIdx.x * 16;
    const float* tq = t + (size_t)(2 * b) * maxr * 64;
    const float* tc = t + (size_t)(2 * b + 1) * maxr * 64;
    int ty = threadIdx.y, tx = threadIdx.x;
    int lin = ty * 16 + tx;
#pragma unroll
    for (int u = 0; u < 4; u++) {
        int idx = lin + u * 256;
        int r = idx / 64, k = idx % 64;
        Tq[r][k] = tq[(size_t)(q0 + r) * 64 + k];
        Tc[r][k] = tc[(size_t)(c0 + r) * 64 + k];
    }
    __syncthreads();
    float s = 0.f;
#pragma unroll
    for (int k = 0; k < 64; k++) s += Tq[ty][k] * Tc[tx][k];
    la[((size_t)b * maxr + q0 + ty) * maxr + c0 + tx] = s * INV_TEMP;
}

// ---------------- fused node Sinkhorn: smem-resident 64x64, 10 iters + exp
__global__ __launch_bounds__(256) void node_sink_kernel(float* __restrict__ la)
{
    __shared__ float L[64][65];
    float* base = la + (size_t)blockIdx.x * 4096;
    int tid = threadIdx.x;
    for (int i = tid; i < 4096; i += 256) L[i >> 6][i & 63] = base[i];
    __syncthreads();
    int r = tid >> 2;
    int part = (tid & 3) * 16;
    for (int iter = 0; iter < SINK_ITERS; iter++) {
        {
            float m = -INFINITY;
#pragma unroll
            for (int i = 0; i < 16; i++) m = fmaxf(m, L[r][part + i]);
            m = fmaxf(m, __shfl_xor_sync(0xFFFFFFFFu, m, 1));
            m = fmaxf(m, __shfl_xor_sync(0xFFFFFFFFu, m, 2));
            float s = 0.f;
#pragma unroll
            for (int i = 0; i < 16; i++) s += expf(L[r][part + i] - m);
            s += __shfl_xor_sync(0xFFFFFFFFu, s, 1);
            s += __shfl_xor_sync(0xFFFFFFFFu, s, 2);
            float lse = m + logf(s);
#pragma unroll
            for (int i = 0; i < 16; i++) L[r][part + i] -= lse;
        }
        __syncthreads();
        {
            float m = -INFINITY;
#pragma unroll
            for (int i = 0; i < 16; i++) m = fmaxf(m, L[part + i][r]);
            m = fmaxf(m, __shfl_xor_sync(0xFFFFFFFFu, m, 1));
            m = fmaxf(m, __shfl_xor_sync(0xFFFFFFFFu, m, 2));
            float s = 0.f;
#pragma unroll
            for (int i = 0; i < 16; i++) s += expf(L[part + i][r] - m);
            s += __shfl_xor_sync(0xFFFFFFFFu, s, 1);
            s += __shfl_xor_sync(0xFFFFFFFFu, s, 2);
            float lse = m + logf(s);
#pragma unroll
            for (int i = 0; i < 16; i++) L[part + i][r] -= lse;
        }
        __syncthreads();
    }
    for (int i = tid; i < 4096; i += 256) base[i] = expf(L[i >> 6][i & 63]);
}

// ---------------- fused edge Sinkhorn: 256x256, 10 iters + exp
__global__ __launch_bounds__(1024) void edge_sink_kernel(float* __restrict__ la)
{
    float* base = la + (size_t)blockIdx.x * 65536;
    int tid = threadIdx.x;
    int wid = tid >> 5, lane = tid & 31;
    __shared__ float cr[4][256];
    int c = tid & 255, g = tid >> 8;
    for (int iter = 0; iter < SINK_ITERS; iter++) {
        for (int r = wid; r < 256; r += 32) {
            float* rp = base + (size_t)r * 256;
            float4 v0 = *(float4*)(rp + lane * 4);
            float4 v1 = *(float4*)(rp + 128 + lane * 4);
            float m = fmaxf(fmaxf(fmaxf(v0.x, v0.y), fmaxf(v0.z, v0.w)),
                            fmaxf(fmaxf(v1.x, v1.y), fmaxf(v1.z, v1.w)));
#pragma unroll
            for (int o = 16; o > 0; o >>= 1) m = fmaxf(m, __shfl_xor_sync(0xFFFFFFFFu, m, o));
            float s = expf(v0.x - m) + expf(v0.y - m) + expf(v0.z - m) + expf(v0.w - m)
                    + expf(v1.x - m) + expf(v1.y - m) + expf(v1.z - m) + expf(v1.w - m);
#pragma unroll
            for (int o = 16; o > 0; o >>= 1) s += __shfl_xor_sync(0xFFFFFFFFu, s, o);
            float lse = m + logf(s);
            v0.x -= lse; v0.y -= lse; v0.z -= lse; v0.w -= lse;
            v1.x -= lse; v1.y -= lse; v1.z -= lse; v1.w -= lse;
            *(float4*)(rp + lane * 4) = v0;
            *(float4*)(rp + 128 + lane * 4) = v1;
        }
        __syncthreads();
        float m = -INFINITY;
        for (int r = g * 64; r < g * 64 + 64; r++) m = fmaxf(m, base[(size_t)r * 256 + c]);
        cr[g][c] = m;
        __syncthreads();
        if (g == 0) cr[0][c] = fmaxf(fmaxf(cr[0][c], cr[1][c]), fmaxf(cr[2][c], cr[3][c]));
        __syncthreads();
        m = cr[0][c];
        float s = 0.f;
        for (int r = g * 64; r < g * 64 + 64; r++) s += expf(base[(size_t)r * 256 + c] - m);
        __syncthreads();
        cr[g][c] = s;
        __syncthreads();
        if (g == 0) cr[0][c] = m + logf(cr[0][c] + cr[1][c] + cr[2][c] + cr[3][c]);
        __syncthreads();
        float lse = cr[0][c];
        bool last = (iter == SINK_ITERS - 1);
        for (int r = g * 64; r < g * 64 + 64; r++) {
            float v = base[(size_t)r * 256 + c] - lse;
            base[(size_t)r * 256 + c] = last ? expf(v) : v;
        }
        __syncthreads();
    }
}

// ---------------- score ----------------
__global__ void score_kernel(const float* __restrict__ upd_node, const float* __restrict__ plan,
                             float* __restrict__ out)
{
    int b = blockIdx.x;
    int t = threadIdx.x;
    __shared__ float P[64][64];
    __shared__ float FC[48][128];
    __shared__ float red[128];
    for (int idx = t; idx < 64 * 64; idx += 128)
        P[idx / 64][idx % 64] = plan[(size_t)b * 4096 + idx];
    for (int idx = t; idx < 48 * 128; idx += 128) {
        int c = idx / 128, d = idx % 128;
        FC[c][d] = upd_node[((size_t)(2 * b + 1) * 48 + c) * 768 + 640 + d];
    }
    __syncthreads();
    float acc = 0.f;
    for (int q = 0; q < 64; q++) {
        float s = 0.f;
#pragma unroll 8
        for (int c = 0; c < 48; c++) s += P[q][c] * FC[c][t];
        float fq = 0.f;
        if (q < 48) fq = upd_node[((size_t)(2 * b) * 48 + q) * 768 + 640 + t];
        acc += fmaxf(fq - s, 0.f);
    }
    red[t] = acc;
    __syncthreads();
    for (int s2 = 64; s2 > 0; s2 >>= 1) {
        if (t < s2) red[t] += red[t + s2];
        __syncthreads();
    }
    if (t == 0) out[b] = -red[0];
}

// ---------------- host helpers ----------------
struct Seg { const float* A; int lda; const int* rows; };

static void bgemmE(cudaStream_t st, Seg s0, Seg s1, int kb1, const float* B, const float* bias,
                   const float* Cin, int ldcin, float cs,
                   float* C, float* Cd, int ldc, int M, int N, int K, int relu, int dual)
{
    dim3 g(N / 128, M / 128, dual ? 2 : 1);
    bgemm_kernel<128><<<g, 256, 0, st>>>(s0.A, s0.lda, s0.rows, s1.A, s1.lda, s1.rows, kb1,
                                         B, bias, Cin, ldcin, cs, C, Cd, ldc, N, K, relu);
}

static void bgemmN(cudaStream_t st, Seg s0, Seg s1, int kb1, const float* B, const float* bias,
                   const float* Cin, int ldcin, float cs,
                   float* C, int ldc, int M, int N, int K, int relu)
{
    dim3 g(N / 128, M / 64, 1);
    bgemm_kernel<64><<<g, 256, 0, st>>>(s0.A, s0.lda, s0.rows, s1.A, s1.lda, s1.rows, kb1,
                                        B, bias, Cin, ldcin, cs, C, nullptr, ldc, N, K, relu);
}

static void zero_buf(cudaStream_t st, float* p, size_t n)
{
    int grid = (int)((n + 255) / 256);
    if (grid > 8192) grid = 8192;
    zero_kernel<<<grid, 256, 0, st>>>(p, n);
}

extern "C" void kernel_launch(void* const* d_in, const int* in_sizes, int n_in,
                              void* d_out, int out_size)
{
    const float* node_features = (const float*)d_in[0];
    const float* edge_features = (const float*)d_in[1];
    const int* from_idx = (const int*)d_in[2];
    const int* to_idx = (const int*)d_in[3];
    const float* enc_node_W = (const float*)d_in[4];
    const float* enc_node_b = (const float*)d_in[5];
    const float* enc_edge_W = (const float*)d_in[6];
    const float* enc_edge_b = (const float*)d_in[7];
    const float* ni_W1 = (const float*)d_in[8];
    const float* ni_b1 = (const float*)d_in[9];
    const float* ni_W2 = (const float*)d_in[10];
    const float* ni_b2 = (const float*)d_in[11];
    const float* ei_W1 = (const float*)d_in[12];
    const float* ei_b1 = (const float*)d_in[13];
    const float* ei_W2 = (const float*)d_in[14];
    const float* ei_b2 = (const float*)d_in[15];
    const float* msg_W = (const float*)d_in[16];
    const float* msg_b = (const float*)d_in[17];
    const float* nu_W1 = (const float*)d_in[18];
    const float* nu_b1 = (const float*)d_in[19];
    const float* nu_W2 = (const float*)d_in[20];
    const float* nu_b2 = (const float*)d_in[21];
    const float* ns_W1 = (const float*)d_in[22];
    const float* ns_b1 = (const float*)d_in[23];
    const float* ns_W2 = (const float*)d_in[24];
    const float* ns_b2 = (const float*)d_in[25];
    const float* es_W1 = (const float*)d_in[26];
    const float* es_b1 = (const float*)d_in[27];
    const float* es_W2 = (const float*)d_in[28];
    const float* es_b2 = (const float*)d_in[29];

    // one-time host resources (no device allocations)
    static cudaStream_t sN = nullptr;
    static cudaEvent_t evFork, evHC, evU, evN;
    if (!sN) {
        cudaStreamCreateWithFlags(&sN, cudaStreamNonBlocking);
        cudaEventCreateWithFlags(&evFork, cudaEventDisableTiming);
        cudaEventCreateWithFlags(&evHC, cudaEventDisableTiming);
        cudaEventCreateWithFlags(&evU, cudaEventDisableTiming);
        cudaEventCreateWithFlags(&evN, cudaEventDisableTiming);
    }
    cudaStream_t sE = 0;  // default (capture) stream = edge lineage

    float* S = nullptr;
    cudaGetSymbolAddress((void**)&S, g_scratch);

    float* enc_n = S + OFF_ENC_N;
    float* enc_e = S + OFF_ENC_E;
    float* node_store = S + OFF_NS;
    float* edge_store = S + OFF_ES;
    float* UN = S + OFF_UN;
    float* UE = S + OFF_UE;
    float* tmpN = S + OFF_TMPN;
    float* tmpE = S + OFF_TMPE;
    float* hcomb = S + OFF_HC;
    float* ecomb = S + OFF_EC;
    float* fwd = S + OFF_FWD;
    float* bwd = S + OFF_BWD;
    float* agg = S + OFF_AGG;
    float* TN = S + OFF_TN;
    float* TE = S + OFF_TE;
    float* PLN = S + OFF_PLN;
    float* PLE = S + OFF_PLE;
    float* ewc = S + OFF_EWC;
    float* wab = S + OFF_WAB;
    int* csr = (int*)(S + OFF_CSR);
    int* deg = csr;
    int* off = csr + VN;
    int* pos = off + VN + 1;
    int* list = pos + VN;

    Seg none{nullptr, 0, nullptr};

    // ---- prep on edge stream, then fork node stream ----
    zero_buf(sE, node_store, SZ_NS);
    zero_buf(sE, edge_store, SZ_ES);
    zero_buf(sE, (float*)deg, VN);
    wab_kernel<<<(128 * 256 + 255) / 256, 256, 0, sE>>>(msg_W, wab);
    count_deg_kernel<<<(VE + 255) / 256, 256, 0, sE>>>(from_idx, to_idx, deg);
    scan_kernel<<<1, 256, 0, sE>>>(deg, off, pos);
    fill_csr_kernel<<<(VE + 255) / 256, 256, 0, sE>>>(from_idx, to_idx, pos, list);

    cudaEventRecord(evFork, sE);
    cudaStreamWaitEvent(sN, evFork, 0);

    // encoders: node on sN, edge on sE
    bgemmN(sN, Seg{node_features, DIN, nullptr}, none, 32,
           enc_node_W, enc_node_b, nullptr, 0, 0.f, enc_n, 128, VN, 128, 32, 0);
    bgemmE(sE, Seg{edge_features, DIN, nullptr}, none, 32,
           enc_edge_W, enc_edge_b, nullptr, 0, 0.f, enc_e, nullptr, 128, VE, 128, 32, 0, 0);

    for (int k = 0; k < KK; k++) {
        for (int p = 1; p <= TT; p++) {
            const float* hptr = (p == 1) ? enc_n : (UN + (size_t)(p - 1) * 128);
            int hlda = (p == 1) ? 128 : 768;

            // node chain on sN: h_comb = mlp2([h | node_store slice], ni)
            if (p >= 2) cudaStreamWaitEvent(sN, evU, 0);  // UN slot p-1 + tmpN free
            bgemmN(sN, Seg{hptr, hlda, nullptr},
                   Seg{node_store + (size_t)(p - 1) * 128, 768, nullptr}, 128,
                   ni_W1, ni_b1, nullptr, 0, 0.f, tmpN, 256, VN, 256, 256, 1);
            bgemmN(sN, Seg{tmpN, 256, nullptr}, none, 256,
                   ni_W2, ni_b2, nullptr, 0, 0.f, hcomb, 128, VN, 128, 256, 0);
            cudaEventRecord(evHC, sN);

            // edge chain on sE (runs concurrently with node chain)
            bgemmE(sE, Seg{enc_e, 128, nullptr},
                   Seg{edge_store + (size_t)(p - 1) * 256, 1536, nullptr}, 128,
                   ei_W1, ei_b1, nullptr, 0, 0.f, tmpE, nullptr, 384, VE, 384, 384, 1, 0);
            bgemmE(sE, Seg{tmpE, 384, nullptr}, none, 384,
                   ei_W2, ei_b2, nullptr, 0, 0.f, ecomb, nullptr, 128, VE, 128, 384, 0, 0);
            bgemmE(sE, Seg{ecomb, 128, nullptr}, none, 128,
                   msg_W + 256 * 256, msg_b, nullptr, 0, 0.f, ewc, nullptr, 256, VE, 256, 128, 0, 0);

            // join: fwd/bwd needs hcomb
            cudaStreamWaitEvent(sE, evHC, 0);
            bgemmE(sE, Seg{hcomb, 128, from_idx}, Seg{hcomb, 128, to_idx}, 128,
                   msg_W, nullptr, ewc, 256, 1.f, fwd, bwd, 256, VE, 256, 256, 0, 1);

            agg_gather_kernel<<<VN, 256, 0, sE>>>(fwd, bwd, off, list, agg);

            // h_new = mlp2([h_comb | agg], nu) -> UN slot p  (on sE: needs agg)
            bgemmN(sE, Seg{hcomb, 128, nullptr}, Seg{agg, 256, nullptr}, 128,
                   nu_W1, nu_b1, nullptr, 0, 0.f, tmpN, 256, VN, 256, 384, 1);
            bgemmN(sE, Seg{tmpN, 256, nullptr}, none, 256,
                   nu_W2, nu_b2, nullptr, 0, 0.f, UN + (size_t)p * 128, 768, VN, 128, 256, 0);
            cudaEventRecord(evU, sE);

            // msgs2 = (h[from]+h[to]) @ (Wa+Wb) + 2*EWc -> UE slot p
            const float* hn = UN + (size_t)p * 128;
            sumsd_kernel<<<(VE * 32 + 255) / 256, 256, 0, sE>>>(hn, from_idx, to_idx, tmpE);
            bgemmE(sE, Seg{tmpE, 128, nullptr}, none, 128,
                   wab, nullptr, ewc, 256, 2.f, UE + (size_t)p * 256, nullptr, 1536, VE, 256, 128, 0, 0);
        }

        // ----- node transport on sN (needs all UN slots) -----
        cudaStreamWaitEvent(sN, evU, 0);
        transport_mlp8_kernel<<<dim3(MAXN / 8, NGRP), 64, 0, sN>>>(
            UN, 768, 640, 128, ns_W1, ns_b1, ns_W2, ns_b2, TN, MAXN, NPER);
        la_kernel<<<dim3(4, 4, BNUM), dim3(16, 16), 0, sN>>>(TN, PLN, MAXN);
        node_sink_kernel<<<BNUM, 256, 0, sN>>>(PLN);
        trans_apply_mma<<<dim3(5, 1, NGRP), 256, 0, sN>>>(PLN, UN, node_store, MAXN, NPER, 768, 128, 64);
        cudaEventRecord(evN, sN);

        // ----- edge transport on sE -----
        transport_mlp8_kernel<<<dim3(MAXE / 8, NGRP), 64, 0, sE>>>(
            UE, 1536, 1280, 256, es_W1, es_b1, es_W2, es_b2, TE, MAXE, EPER);
        la_kernel<<<dim3(16, 16, BNUM), dim3(16, 16), 0, sE>>>(TE, PLE, MAXE);
        edge_sink_kernel<<<BNUM, 1024, 0, sE>>>(PLE);
        trans_apply_mma<<<dim3(10, 3, NGRP), 256, 0, sE>>>(PLE, UE, edge_store, MAXE, EPER, 1536, 256, 192);
    }

    // ----- score: join node lineage back into sE -----
    cudaStreamWaitEvent(sE, evN, 0);
    score_kernel<<<BNUM, 128, 0, sE>>>(UN, PLN, (float*)d_out);
}